// round 1
// baseline (speedup 1.0000x reference)
#include <cuda_runtime.h>
#include <math.h>

#define VOCAB 100000
#define EMB   100
#define HID   100
#define CTX   60
#define FACT  20
#define T     60

// ---------------- scratch (no allocations allowed) ----------------
__device__ float g_facts[CTX * EMB];       // 6000
__device__ float g_h0[HID];
__device__ float g_gi[T * 3 * HID];        // 18000
__device__ float g_H[T * HID];             // 6000
__device__ float g_sumexp[T];
__device__ float g_toklogit[T];

__device__ __forceinline__ float sigmoidf_(float x) {
    return 1.0f / (1.0f + __expf(-x));
}

// ---------------- K1: facts + zero sumexp ----------------
// grid 60, block 100. block f, thread e.
__global__ void k_facts(const int* __restrict__ ctx,
                        const float* __restrict__ emb_ctx) {
    int f = blockIdx.x;
    int e = threadIdx.x;
    if (f == 0 && e < T) g_sumexp[e] = 0.0f;
    __shared__ int toks[FACT];
    if (e < FACT) toks[e] = ctx[f * FACT + e];
    __syncthreads();
    float ee = (float)e * (1.0f / 99.0f);
    float acc = 0.0f;
#pragma unroll
    for (int p = 0; p < FACT; p++) {
        float s = (float)p * (1.0f / 19.0f);
        float l = 1.0f - s - ee * (1.0f - 2.0f * s);
        acc += emb_ctx[(long)toks[p] * EMB + e] * l;
    }
    g_facts[f * EMB + e] = acc;
}

// ---------------- K2: h0[j] = b1[j] + facts_flat . w1[j,:] ----------------
// grid 100, block 256.
__global__ void k_h0(const float* __restrict__ w1, const float* __restrict__ b1) {
    int j = blockIdx.x;
    int tid = threadIdx.x;
    const float* wr = w1 + (long)j * (CTX * HID);
    float acc = 0.0f;
    for (int k = tid; k < CTX * HID; k += 256)
        acc += g_facts[k] * wr[k];
    // block reduce
    for (int off = 16; off; off >>= 1)
        acc += __shfl_down_sync(0xffffffffu, acc, off);
    __shared__ float s[8];
    if ((tid & 31) == 0) s[tid >> 5] = acc;
    __syncthreads();
    if (tid == 0) {
        float tot = 0.0f;
#pragma unroll
        for (int w = 0; w < 8; w++) tot += s[w];
        g_h0[j] = tot + b1[j];
    }
}

// ---------------- K2b: gi[t][j] = b_ih[j] + w_ih[j,:] . x_t ----------------
// grid 60, block 320.
__global__ void k_gi(const int* __restrict__ desc,
                     const float* __restrict__ emb_dec,
                     const float* __restrict__ w_ih,
                     const float* __restrict__ b_ih) {
    int t = blockIdx.x;
    int j = threadIdx.x;
    __shared__ __align__(16) float x[EMB];
    __shared__ int tok;
    if (j == 0) tok = (t == 0) ? 1 : desc[t - 1];
    __syncthreads();
    if (j < EMB) x[j] = emb_dec[(long)tok * EMB + j];
    __syncthreads();
    if (j < 3 * HID) {
        const float4* w4 = (const float4*)(w_ih + (long)j * EMB);
        const float4* x4 = (const float4*)x;
        float a0 = b_ih[j], a1 = 0.0f, a2 = 0.0f, a3 = 0.0f;
#pragma unroll
        for (int k = 0; k < 25; k++) {
            float4 w = w4[k];
            float4 h = x4[k];
            a0 += w.x * h.x; a1 += w.y * h.y; a2 += w.z * h.z; a3 += w.w * h.w;
        }
        g_gi[t * (3 * HID) + j] = (a0 + a1) + (a2 + a3);
    }
}

// ---------------- K3: sequential GRU recurrence ----------------
// single block, 320 threads. w_hh rows register-resident.
__global__ void __launch_bounds__(320, 1) k_rnn(const float* __restrict__ w_hh,
                                                const float* __restrict__ b_hh) {
    int j = threadIdx.x;
    float w[HID];
    float bh = 0.0f;
    if (j < 3 * HID) {
        const float4* w4 = (const float4*)(w_hh + (long)j * HID);
#pragma unroll
        for (int k = 0; k < 25; k++) {
            float4 v = w4[k];
            w[4 * k + 0] = v.x; w[4 * k + 1] = v.y;
            w[4 * k + 2] = v.z; w[4 * k + 3] = v.w;
        }
        bh = b_hh[j];
    }
    __shared__ __align__(16) float h[HID];
    __shared__ float gh[3 * HID];
    if (j < HID) h[j] = g_h0[j];
    __syncthreads();

    for (int t = 0; t < T; t++) {
        if (j < 3 * HID) {
            const float4* h4 = (const float4*)h;
            float a0 = bh, a1 = 0.0f, a2 = 0.0f, a3 = 0.0f;
#pragma unroll
            for (int k = 0; k < 25; k++) {
                float4 hv = h4[k];
                a0 += w[4 * k + 0] * hv.x;
                a1 += w[4 * k + 1] * hv.y;
                a2 += w[4 * k + 2] * hv.z;
                a3 += w[4 * k + 3] * hv.w;
            }
            gh[j] = (a0 + a1) + (a2 + a3);
        }
        __syncthreads();
        if (j < HID) {
            const float* gi = g_gi + t * (3 * HID);
            float r = sigmoidf_(gi[j] + gh[j]);
            float z = sigmoidf_(gi[HID + j] + gh[HID + j]);
            float n = tanhf(gi[2 * HID + j] + r * gh[2 * HID + j]);
            float hn = (1.0f - z) * n + z * h[j];
            h[j] = hn;
            g_H[t * HID + j] = hn;
        }
        __syncthreads();
    }
}

// ---------------- K4: logits GEMM + per-step sum(exp) + target logit ----------------
// grid 391, block 256. Thread owns one vocab row, w_out row in registers.
__global__ void __launch_bounds__(256) k_logits(const float* __restrict__ w_out,
                                                const float* __restrict__ b_out,
                                                const int* __restrict__ desc) {
    __shared__ __align__(16) float sH[T * HID];
    __shared__ int stok[T];
    __shared__ float ssum[T];
    int tid = threadIdx.x;
    for (int i = tid; i < T * HID; i += 256) sH[i] = g_H[i];
    if (tid < T) { stok[tid] = desc[tid]; ssum[tid] = 0.0f; }
    __syncthreads();

    int v = blockIdx.x * 256 + tid;
    bool valid = (v < VOCAB);
    float w[HID];
    float bo = 0.0f;
    if (valid) {
        const float4* w4 = (const float4*)(w_out + (long)v * HID);
#pragma unroll
        for (int k = 0; k < 25; k++) {
            float4 x = w4[k];
            w[4 * k + 0] = x.x; w[4 * k + 1] = x.y;
            w[4 * k + 2] = x.z; w[4 * k + 3] = x.w;
        }
        bo = b_out[v];
    }
    int lane = tid & 31;

    for (int t = 0; t < T; t++) {
        float a0 = bo, a1 = 0.0f, a2 = 0.0f, a3 = 0.0f;
        const float4* h4 = (const float4*)(sH + t * HID);
#pragma unroll
        for (int k = 0; k < 25; k++) {
            float4 hv = h4[k];
            a0 += w[4 * k + 0] * hv.x;
            a1 += w[4 * k + 1] * hv.y;
            a2 += w[4 * k + 2] * hv.z;
            a3 += w[4 * k + 3] * hv.w;
        }
        float logit = (a0 + a1) + (a2 + a3);
        float e = valid ? __expf(logit) : 0.0f;
        // warp reduce
        for (int off = 16; off; off >>= 1)
            e += __shfl_down_sync(0xffffffffu, e, off);
        if (lane == 0) atomicAdd(&ssum[t], e);
        if (valid && v == stok[t]) g_toklogit[t] = logit;
    }
    __syncthreads();
    if (tid < T) atomicAdd(&g_sumexp[tid], ssum[tid]);
}

// ---------------- K5: final loss reduction ----------------
__global__ void k_final(float* __restrict__ out) {
    int t = threadIdx.x; // 64 threads
    float v = 0.0f;
    if (t < T) v = logf(g_sumexp[t]) - g_toklogit[t];
    for (int off = 16; off; off >>= 1)
        v += __shfl_down_sync(0xffffffffu, v, off);
    __shared__ float s[2];
    if ((t & 31) == 0) s[t >> 5] = v;
    __syncthreads();
    if (t == 0) out[0] = s[0] + s[1];
}

// ---------------- launch ----------------
extern "C" void kernel_launch(void* const* d_in, const int* in_sizes, int n_in,
                              void* d_out, int out_size) {
    const int*   context  = (const int*)d_in[0];
    // d_in[1] = fact_lengths (unused by reference)
    const int*   desc     = (const int*)d_in[2];
    const float* emb_ctx  = (const float*)d_in[3];
    const float* emb_dec  = (const float*)d_in[4];
    const float* w1       = (const float*)d_in[5];
    const float* b1       = (const float*)d_in[6];
    const float* w_ih     = (const float*)d_in[7];
    const float* w_hh     = (const float*)d_in[8];
    const float* b_ih     = (const float*)d_in[9];
    const float* b_hh     = (const float*)d_in[10];
    const float* w_out    = (const float*)d_in[11];
    const float* b_out    = (const float*)d_in[12];
    float* out = (float*)d_out;

    k_facts<<<CTX, 100>>>(context, emb_ctx);
    k_h0<<<HID, 256>>>(w1, b1);
    k_gi<<<T, 320>>>(desc, emb_dec, w_ih, b_ih);
    k_rnn<<<1, 320>>>(w_hh, b_hh);
    k_logits<<<(VOCAB + 255) / 256, 256>>>(w_out, b_out, desc);
    k_final<<<1, 64>>>(out);
}

// round 2
// speedup vs baseline: 1.2192x; 1.2192x over previous
#include <cuda_runtime.h>
#include <math.h>

#define VOCAB 100000
#define EMB   100
#define HID   100
#define CTX   60
#define FACT  20
#define T     60

typedef unsigned long long u64;

// ---------------- scratch ----------------
__device__ float g_facts[CTX * EMB];
__device__ float g_h0[HID];
__device__ float g_gi[T * 3 * HID];
__device__ float g_H[T * HID];
__device__ float g_sumexp[T];
__device__ float g_toklogit[T];

__device__ __forceinline__ float sigmoidf_(float x) {
    return 1.0f / (1.0f + __expf(-x));
}

// packed f32x2 fused multiply-add: d = a*b + d (elementwise on 2 packed floats)
__device__ __forceinline__ void ffma2(u64 &d, u64 a, u64 b) {
    asm("fma.rn.f32x2 %0, %1, %2, %0;" : "+l"(d) : "l"(a), "l"(b));
}
__device__ __forceinline__ float f2_lo(u64 v) { return __int_as_float((int)(v & 0xffffffffull)); }
__device__ __forceinline__ float f2_hi(u64 v) { return __int_as_float((int)(v >> 32)); }
__device__ __forceinline__ u64 f2_pack(float x, float y) {
    return (u64)__float_as_uint(x) | ((u64)__float_as_uint(y) << 32);
}

// ---------------- K1: facts + zero sumexp ----------------
__global__ void k_facts(const int* __restrict__ ctx,
                        const float* __restrict__ emb_ctx) {
    int f = blockIdx.x;
    int e = threadIdx.x;
    if (f == 0 && e < T) g_sumexp[e] = 0.0f;
    __shared__ int toks[FACT];
    if (e < FACT) toks[e] = ctx[f * FACT + e];
    __syncthreads();
    float ee = (float)e * (1.0f / 99.0f);
    float acc = 0.0f;
#pragma unroll
    for (int p = 0; p < FACT; p++) {
        float s = (float)p * (1.0f / 19.0f);
        float l = 1.0f - s - ee * (1.0f - 2.0f * s);
        acc += emb_ctx[(long)toks[p] * EMB + e] * l;
    }
    g_facts[f * EMB + e] = acc;
}

// ---------------- K2: h0 ----------------
__global__ void k_h0(const float* __restrict__ w1, const float* __restrict__ b1) {
    int j = blockIdx.x;
    int tid = threadIdx.x;
    const float* wr = w1 + (long)j * (CTX * HID);
    float acc = 0.0f;
    for (int k = tid; k < CTX * HID; k += 256)
        acc += g_facts[k] * wr[k];
    for (int off = 16; off; off >>= 1)
        acc += __shfl_down_sync(0xffffffffu, acc, off);
    __shared__ float s[8];
    if ((tid & 31) == 0) s[tid >> 5] = acc;
    __syncthreads();
    if (tid == 0) {
        float tot = 0.0f;
#pragma unroll
        for (int w = 0; w < 8; w++) tot += s[w];
        g_h0[j] = tot + b1[j];
    }
}

// ---------------- K2b: gi[t][j] ----------------
__global__ void k_gi(const int* __restrict__ desc,
                     const float* __restrict__ emb_dec,
                     const float* __restrict__ w_ih,
                     const float* __restrict__ b_ih) {
    int t = blockIdx.x;
    int j = threadIdx.x;
    __shared__ __align__(16) float x[EMB];
    __shared__ int tok;
    if (j == 0) tok = (t == 0) ? 1 : desc[t - 1];
    __syncthreads();
    if (j < EMB) x[j] = emb_dec[(long)tok * EMB + j];
    __syncthreads();
    if (j < 3 * HID) {
        const float4* w4 = (const float4*)(w_ih + (long)j * EMB);
        const float4* x4 = (const float4*)x;
        float a0 = b_ih[j], a1 = 0.0f, a2 = 0.0f, a3 = 0.0f;
#pragma unroll
        for (int k = 0; k < 25; k++) {
            float4 w = w4[k];
            float4 h = x4[k];
            a0 += w.x * h.x; a1 += w.y * h.y; a2 += w.z * h.z; a3 += w.w * h.w;
        }
        g_gi[t * (3 * HID) + j] = (a0 + a1) + (a2 + a3);
    }
}

// ---------------- K3: sequential GRU recurrence ----------------
// 600 threads. Output j handled by threads j (K 0..49) and j+300 (K 50..99).
// Per-thread weights: 25 packed f32x2 registers.
__global__ void __launch_bounds__(600, 1) k_rnn(const float* __restrict__ w_hh,
                                                const float* __restrict__ b_hh) {
    int tid = threadIdx.x;
    int out = tid % 300;
    int half = tid / 300;

    u64 w2[25];
    {
        const u64* wr = (const u64*)(w_hh + (long)out * HID + half * 50);
#pragma unroll
        for (int k = 0; k < 25; k++) w2[k] = wr[k];
    }
    float bh = (tid < 300) ? b_hh[tid] : 0.0f;

    __shared__ __align__(16) float h[HID];
    __shared__ float ps[600];
    __shared__ float ghs[3 * HID];
    __shared__ float gis[3 * HID];
    if (tid < HID) h[tid] = g_h0[tid];
    __syncthreads();

    for (int t = 0; t < T; t++) {
        // issue global gi load early; consumed after 2 barriers
        float gi_mine = (tid < 300) ? g_gi[t * 300 + tid] : 0.0f;

        // phase 1: partial dot (25 packed FMA on shared h)
        {
            const u64* h2 = (const u64*)(h + half * 50);
            u64 acc = 0ull; // == (0.0f, 0.0f)
#pragma unroll
            for (int k = 0; k < 25; k++) ffma2(acc, w2[k], h2[k]);
            ps[tid] = f2_lo(acc) + f2_hi(acc);
        }
        __syncthreads();

        // phase 2: combine halves
        if (tid < 300) {
            ghs[tid] = ps[tid] + ps[tid + 300] + bh;
            gis[tid] = gi_mine;
        }
        __syncthreads();

        // phase 3: gate nonlinearities + h update
        if (tid < HID) {
            float r = sigmoidf_(gis[tid] + ghs[tid]);
            float z = sigmoidf_(gis[HID + tid] + ghs[HID + tid]);
            float a = gis[2 * HID + tid] + r * ghs[2 * HID + tid];
            float ex = __expf(2.0f * a);
            float n = 1.0f - __fdividef(2.0f, ex + 1.0f);
            float hn = (1.0f - z) * n + z * h[tid];
            h[tid] = hn;
            g_H[t * HID + tid] = hn;
        }
        __syncthreads();
    }
}

// ---------------- K4: logits GEMM + per-step sum(exp) + target logit ----------------
// block 128, grid 782. One vocab row per thread, weights as 50 packed f32x2 regs.
#define LB 128
__global__ void __launch_bounds__(LB) k_logits(const float* __restrict__ w_out,
                                               const float* __restrict__ b_out,
                                               const int* __restrict__ desc) {
    __shared__ __align__(16) float sH[T * HID];
    __shared__ int stok[T];
    __shared__ float ssum[T];
    int tid = threadIdx.x;
    for (int i = tid; i < T * HID; i += LB) sH[i] = g_H[i];
    if (tid < T) { stok[tid] = desc[tid]; ssum[tid] = 0.0f; }
    __syncthreads();

    int v = blockIdx.x * LB + tid;
    bool valid = (v < VOCAB);
    u64 w2[50];
    float bo = 0.0f;
    if (valid) {
        const u64* wr = (const u64*)(w_out + (size_t)v * HID);
#pragma unroll
        for (int k = 0; k < 50; k++) w2[k] = wr[k];
        bo = b_out[v];
    }
    int lane = tid & 31;

    for (int t = 0; t < T; t++) {
        const u64* h2 = (const u64*)(sH + t * HID);
        u64 acc = f2_pack(bo, 0.0f);
#pragma unroll
        for (int k = 0; k < 50; k++) ffma2(acc, w2[k], h2[k]);
        float logit = f2_lo(acc) + f2_hi(acc);
        float e = valid ? __expf(logit) : 0.0f;
        for (int off = 16; off; off >>= 1)
            e += __shfl_down_sync(0xffffffffu, e, off);
        if (lane == 0) atomicAdd(&ssum[t], e);
        if (valid && v == stok[t]) g_toklogit[t] = logit;
    }
    __syncthreads();
    if (tid < T) atomicAdd(&g_sumexp[tid], ssum[tid]);
}

// ---------------- K5: final loss ----------------
__global__ void k_final(float* __restrict__ out) {
    int t = threadIdx.x;
    float v = 0.0f;
    if (t < T) v = logf(g_sumexp[t]) - g_toklogit[t];
    for (int off = 16; off; off >>= 1)
        v += __shfl_down_sync(0xffffffffu, v, off);
    __shared__ float s[2];
    if ((t & 31) == 0) s[t >> 5] = v;
    __syncthreads();
    if (t == 0) out[0] = s[0] + s[1];
}

// ---------------- launch ----------------
extern "C" void kernel_launch(void* const* d_in, const int* in_sizes, int n_in,
                              void* d_out, int out_size) {
    const int*   context  = (const int*)d_in[0];
    const int*   desc     = (const int*)d_in[2];
    const float* emb_ctx  = (const float*)d_in[3];
    const float* emb_dec  = (const float*)d_in[4];
    const float* w1       = (const float*)d_in[5];
    const float* b1       = (const float*)d_in[6];
    const float* w_ih     = (const float*)d_in[7];
    const float* w_hh     = (const float*)d_in[8];
    const float* b_ih     = (const float*)d_in[9];
    const float* b_hh     = (const float*)d_in[10];
    const float* w_out    = (const float*)d_in[11];
    const float* b_out    = (const float*)d_in[12];
    float* out = (float*)d_out;

    k_facts<<<CTX, 100>>>(context, emb_ctx);
    k_h0<<<HID, 256>>>(w1, b1);
    k_gi<<<T, 320>>>(desc, emb_dec, w_ih, b_ih);
    k_rnn<<<1, 600>>>(w_hh, b_hh);
    k_logits<<<(VOCAB + LB - 1) / LB, LB>>>(w_out, b_out, desc);
    k_final<<<1, 64>>>(out);
}

// round 3
// speedup vs baseline: 1.2828x; 1.0521x over previous
#include <cuda_runtime.h>
#include <math.h>

#define VOCAB 100000
#define EMB   100
#define HID   100
#define CTX   60
#define FACT  20
#define T     60

typedef unsigned long long u64;

// ---------------- scratch ----------------
__device__ float g_facts[CTX * EMB];
__device__ float g_h0[HID];
__device__ float g_gi[T * 3 * HID];
__device__ float g_H[T * HID];
__device__ float g_sumexp[T];
__device__ float g_toklogit[T];

__device__ __forceinline__ float sigmoidf_(float x) {
    return 1.0f / (1.0f + __expf(-x));
}
__device__ __forceinline__ void ffma2(u64 &d, u64 a, u64 b) {
    asm("fma.rn.f32x2 %0, %1, %2, %0;" : "+l"(d) : "l"(a), "l"(b));
}
__device__ __forceinline__ float f2_lo(u64 v) { return __int_as_float((int)(v & 0xffffffffull)); }
__device__ __forceinline__ float f2_hi(u64 v) { return __int_as_float((int)(v >> 32)); }
__device__ __forceinline__ u64 f2_pack(float x, float y) {
    return (u64)__float_as_uint(x) | ((u64)__float_as_uint(y) << 32);
}

// ---------------- K_pre: facts (blocks 60..119) + gi (blocks 0..59) ----------------
__global__ void __launch_bounds__(320) k_pre(const int* __restrict__ ctx,
                                             const float* __restrict__ emb_ctx,
                                             const int* __restrict__ desc,
                                             const float* __restrict__ emb_dec,
                                             const float* __restrict__ w_ih,
                                             const float* __restrict__ b_ih) {
    int bid = blockIdx.x;
    int j = threadIdx.x;
    if (bid < 60) {
        // gi[t][j] = b_ih[j] + w_ih[j,:] . x_t
        int t = bid;
        __shared__ __align__(16) float x[EMB];
        __shared__ int tok;
        if (j == 0) tok = (t == 0) ? 1 : desc[t - 1];
        __syncthreads();
        if (j < EMB) x[j] = emb_dec[(long)tok * EMB + j];
        __syncthreads();
        if (j < 3 * HID) {
            const float4* w4 = (const float4*)(w_ih + (long)j * EMB);
            const float4* x4 = (const float4*)x;
            float a0 = b_ih[j], a1 = 0.0f, a2 = 0.0f, a3 = 0.0f;
#pragma unroll
            for (int k = 0; k < 25; k++) {
                float4 w = w4[k];
                float4 h = x4[k];
                a0 += w.x * h.x; a1 += w.y * h.y; a2 += w.z * h.z; a3 += w.w * h.w;
            }
            g_gi[t * (3 * HID) + j] = (a0 + a1) + (a2 + a3);
        }
    } else {
        // facts
        int f = bid - 60;
        if (f == 0 && j < T) g_sumexp[j] = 0.0f;
        __shared__ int toks[FACT];
        if (j < FACT) toks[j] = ctx[f * FACT + j];
        __syncthreads();
        if (j < EMB) {
            float ee = (float)j * (1.0f / 99.0f);
            float acc = 0.0f;
#pragma unroll
            for (int p = 0; p < FACT; p++) {
                float s = (float)p * (1.0f / 19.0f);
                float l = 1.0f - s - ee * (1.0f - 2.0f * s);
                acc += emb_ctx[(long)toks[p] * EMB + j] * l;
            }
            g_facts[f * EMB + j] = acc;
        }
    }
}

// ---------------- K2: h0 ----------------
__global__ void k_h0(const float* __restrict__ w1, const float* __restrict__ b1) {
    int j = blockIdx.x;
    int tid = threadIdx.x;
    const float* wr = w1 + (long)j * (CTX * HID);
    float acc = 0.0f;
    for (int k = tid; k < CTX * HID; k += 256)
        acc += g_facts[k] * wr[k];
    for (int off = 16; off; off >>= 1)
        acc += __shfl_down_sync(0xffffffffu, acc, off);
    __shared__ float s[8];
    if ((tid & 31) == 0) s[tid >> 5] = acc;
    __syncthreads();
    if (tid == 0) {
        float tot = 0.0f;
#pragma unroll
        for (int w = 0; w < 8; w++) tot += s[w];
        g_h0[j] = tot + b1[j];
    }
}

// ---------------- K3: GRU recurrence ----------------
// 600 threads. out = tid%300, half = tid/300 (which 50-element K chunk).
// All gi preloaded to shared; 2 barriers/step; dual FFMA2 chains.
__global__ void __launch_bounds__(600, 1) k_rnn(const float* __restrict__ w_hh,
                                                const float* __restrict__ b_hh) {
    extern __shared__ __align__(16) float dyn[];
    float* sgi = dyn;            // 18000
    float* h   = dyn + 18000;    // 100  (byte offset 72000, 8B-aligned)
    float* ps  = h + 100;        // 600

    int tid = threadIdx.x;
    int out = tid % 300;
    int half = tid / 300;

    // register-resident half-row of w_hh (25 packed f32x2)
    u64 w2[25];
    {
        const u64* wr = (const u64*)(w_hh + (long)out * HID + half * 50);
#pragma unroll
        for (int k = 0; k < 25; k++) w2[k] = wr[k];
    }
    // gate-thread private biases
    float bhr = 0.0f, bhz = 0.0f, bhn = 0.0f;
    if (tid < HID) {
        bhr = b_hh[tid];
        bhz = b_hh[HID + tid];
        bhn = b_hh[2 * HID + tid];
    }

    // preload all gi into shared (coalesced)
    for (int i = tid; i < T * 3 * HID; i += 600) sgi[i] = g_gi[i];
    if (tid < HID) h[tid] = g_h0[tid];
    __syncthreads();

    for (int t = 0; t < T; t++) {
        // phase 1: partial dot, dual chains
        {
            const u64* h2 = (const u64*)(h + half * 50);
            u64 a0 = 0ull, a1 = 0ull;
#pragma unroll
            for (int k = 0; k < 12; k++) {
                ffma2(a0, w2[2 * k], h2[2 * k]);
                ffma2(a1, w2[2 * k + 1], h2[2 * k + 1]);
            }
            ffma2(a0, w2[24], h2[24]);
            ps[tid] = (f2_lo(a0) + f2_hi(a0)) + (f2_lo(a1) + f2_hi(a1));
        }
        __syncthreads();

        // phase 2: gates + h update (threads 0..99)
        if (tid < HID) {
            float ghr = ps[tid]           + ps[tid + 300] + bhr;
            float ghz = ps[tid + 100]     + ps[tid + 400] + bhz;
            float ghn = ps[tid + 200]     + ps[tid + 500] + bhn;
            const float* gi = sgi + t * 300;
            float r = sigmoidf_(gi[tid] + ghr);
            float z = sigmoidf_(gi[HID + tid] + ghz);
            float a = gi[2 * HID + tid] + r * ghn;
            float ex = __expf(2.0f * a);
            float n = 1.0f - __fdividef(2.0f, ex + 1.0f);
            float hn = (1.0f - z) * n + z * h[tid];
            h[tid] = hn;
            g_H[t * HID + tid] = hn;
        }
        __syncthreads();
    }
}

// ---------------- K4: logits + per-step sum(exp) + target logit ----------------
#define LB 128
__global__ void __launch_bounds__(LB) k_logits(const float* __restrict__ w_out,
                                               const float* __restrict__ b_out,
                                               const int* __restrict__ desc) {
    __shared__ __align__(16) float sH[T * HID];
    __shared__ int stok[T];
    __shared__ float ssum[T];
    int tid = threadIdx.x;
    int v = blockIdx.x * LB + tid;
    bool valid = (v < VOCAB);

    // issue weight loads first (LDG.128), overlap with sH staging
    u64 w2[50];
    float bo = 0.0f;
    if (valid) {
        const double2* wr = (const double2*)(w_out + (size_t)v * HID);
#pragma unroll
        for (int k = 0; k < 25; k++) {
            double2 d = wr[k];
            w2[2 * k]     = (u64)__double_as_longlong(d.x);
            w2[2 * k + 1] = (u64)__double_as_longlong(d.y);
        }
        bo = b_out[v];
    }
    for (int i = tid; i < T * HID; i += LB) sH[i] = g_H[i];
    if (tid < T) { stok[tid] = desc[tid]; ssum[tid] = 0.0f; }
    __syncthreads();

    int lane = tid & 31;
    for (int t = 0; t < T; t++) {
        const u64* h2 = (const u64*)(sH + t * HID);
        u64 a0 = f2_pack(bo, 0.0f), a1 = 0ull;
#pragma unroll
        for (int k = 0; k < 25; k++) {
            ffma2(a0, w2[2 * k], h2[2 * k]);
            ffma2(a1, w2[2 * k + 1], h2[2 * k + 1]);
        }
        float logit = (f2_lo(a0) + f2_hi(a0)) + (f2_lo(a1) + f2_hi(a1));
        float e = valid ? __expf(logit) : 0.0f;
        for (int off = 16; off; off >>= 1)
            e += __shfl_down_sync(0xffffffffu, e, off);
        if (lane == 0) atomicAdd(&ssum[t], e);
        if (valid && v == stok[t]) g_toklogit[t] = logit;
    }
    __syncthreads();
    if (tid < T) atomicAdd(&g_sumexp[tid], ssum[tid]);
}

// ---------------- K5: final loss ----------------
__global__ void k_final(float* __restrict__ out) {
    int t = threadIdx.x;
    float v = 0.0f;
    if (t < T) v = logf(g_sumexp[t]) - g_toklogit[t];
    for (int off = 16; off; off >>= 1)
        v += __shfl_down_sync(0xffffffffu, v, off);
    __shared__ float s[2];
    if ((t & 31) == 0) s[t >> 5] = v;
    __syncthreads();
    if (t == 0) out[0] = s[0] + s[1];
}

// ---------------- launch ----------------
extern "C" void kernel_launch(void* const* d_in, const int* in_sizes, int n_in,
                              void* d_out, int out_size) {
    const int*   context  = (const int*)d_in[0];
    const int*   desc     = (const int*)d_in[2];
    const float* emb_ctx  = (const float*)d_in[3];
    const float* emb_dec  = (const float*)d_in[4];
    const float* w1       = (const float*)d_in[5];
    const float* b1       = (const float*)d_in[6];
    const float* w_ih     = (const float*)d_in[7];
    const float* w_hh     = (const float*)d_in[8];
    const float* b_ih     = (const float*)d_in[9];
    const float* b_hh     = (const float*)d_in[10];
    const float* w_out    = (const float*)d_in[11];
    const float* b_out    = (const float*)d_in[12];
    float* out = (float*)d_out;

    const int rnn_smem = (T * 3 * HID + HID + 600) * (int)sizeof(float); // 74800 B
    cudaFuncSetAttribute(k_rnn, cudaFuncAttributeMaxDynamicSharedMemorySize, rnn_smem);

    k_pre<<<120, 320>>>(context, emb_ctx, desc, emb_dec, w_ih, b_ih);
    k_h0<<<HID, 256>>>(w1, b1);
    k_rnn<<<1, 600, rnn_smem>>>(w_hh, b_hh);
    k_logits<<<(VOCAB + LB - 1) / LB, LB>>>(w_out, b_out, desc);
    k_final<<<1, 64>>>(out);
}

// round 4
// speedup vs baseline: 1.3745x; 1.0715x over previous
#include <cuda_runtime.h>
#include <math.h>

#define VOCAB 100000
#define EMB   100
#define HID   100
#define CTX   60
#define FACT  20
#define T     60

typedef unsigned long long u64;

// ---------------- scratch ----------------
__device__ float g_facts[CTX * EMB];
__device__ float g_h0[HID];
__device__ float g_gi[T * 3 * HID];
__device__ float g_H[T * HID];            // compact layout (k_final)
__device__ float g_Hp[T * 104];           // padded: [t][half*52 + j], pads stay 0 (zero-init)
__device__ float g_sumexp[T];

__device__ __forceinline__ float sigmoidf_(float x) {
    return 1.0f / (1.0f + __expf(-x));
}
__device__ __forceinline__ void ffma2(u64 &d, u64 a, u64 b) {
    asm("fma.rn.f32x2 %0, %1, %2, %0;" : "+l"(d) : "l"(a), "l"(b));
}
__device__ __forceinline__ float f2_lo(u64 v) { return __int_as_float((int)(v & 0xffffffffull)); }
__device__ __forceinline__ float f2_hi(u64 v) { return __int_as_float((int)(v >> 32)); }
__device__ __forceinline__ u64 f2_pack(float x, float y) {
    return (u64)__float_as_uint(x) | ((u64)__float_as_uint(y) << 32);
}

// ---------------- K_pre: gi (blocks 0..59) + facts (blocks 60..119) ----------------
__global__ void __launch_bounds__(320) k_pre(const int* __restrict__ ctx,
                                             const float* __restrict__ emb_ctx,
                                             const int* __restrict__ desc,
                                             const float* __restrict__ emb_dec,
                                             const float* __restrict__ w_ih,
                                             const float* __restrict__ b_ih) {
    int bid = blockIdx.x;
    int j = threadIdx.x;
    if (bid < 60) {
        int t = bid;
        __shared__ __align__(16) float x[EMB];
        __shared__ int tok;
        if (j == 0) tok = (t == 0) ? 1 : desc[t - 1];
        __syncthreads();
        if (j < EMB) x[j] = emb_dec[(long)tok * EMB + j];
        __syncthreads();
        if (j < 3 * HID) {
            const float4* w4 = (const float4*)(w_ih + (long)j * EMB);
            const float4* x4 = (const float4*)x;
            float a0 = b_ih[j], a1 = 0.0f, a2 = 0.0f, a3 = 0.0f;
#pragma unroll
            for (int k = 0; k < 25; k++) {
                float4 w = w4[k];
                float4 h = x4[k];
                a0 += w.x * h.x; a1 += w.y * h.y; a2 += w.z * h.z; a3 += w.w * h.w;
            }
            g_gi[t * (3 * HID) + j] = (a0 + a1) + (a2 + a3);
        }
    } else {
        int f = bid - 60;
        if (f == 0 && j < T) g_sumexp[j] = 0.0f;
        __shared__ int toks[FACT];
        if (j < FACT) toks[j] = ctx[f * FACT + j];
        __syncthreads();
        if (j < EMB) {
            float ee = (float)j * (1.0f / 99.0f);
            float acc = 0.0f;
#pragma unroll
            for (int p = 0; p < FACT; p++) {
                float s = (float)p * (1.0f / 19.0f);
                float l = 1.0f - s - ee * (1.0f - 2.0f * s);
                acc += emb_ctx[(long)toks[p] * EMB + j] * l;
            }
            g_facts[f * EMB + j] = acc;
        }
    }
}

// ---------------- K2: h0 ----------------
__global__ void k_h0(const float* __restrict__ w1, const float* __restrict__ b1) {
    int j = blockIdx.x;
    int tid = threadIdx.x;
    const float* wr = w1 + (long)j * (CTX * HID);
    float acc = 0.0f;
    for (int k = tid; k < CTX * HID; k += 256)
        acc += g_facts[k] * wr[k];
    for (int off = 16; off; off >>= 1)
        acc += __shfl_down_sync(0xffffffffu, acc, off);
    __shared__ float s[8];
    if ((tid & 31) == 0) s[tid >> 5] = acc;
    __syncthreads();
    if (tid == 0) {
        float tot = 0.0f;
#pragma unroll
        for (int w = 0; w < 8; w++) tot += s[w];
        g_h0[j] = tot + b1[j];
    }
}

// ---------------- K3: GRU recurrence (600 thr, gi in smem, 2 bars/step) ----------------
__global__ void __launch_bounds__(600, 1) k_rnn(const float* __restrict__ w_hh,
                                                const float* __restrict__ b_hh) {
    extern __shared__ __align__(16) float dyn[];
    float* sgi = dyn;            // 18000
    float* h   = dyn + 18000;    // 100
    float* ps  = h + 100;        // 600

    int tid = threadIdx.x;
    int out = tid % 300;
    int half = tid / 300;

    u64 w2[25];
    {
        const u64* wr = (const u64*)(w_hh + (long)out * HID + half * 50);
#pragma unroll
        for (int k = 0; k < 25; k++) w2[k] = wr[k];
    }
    float bhr = 0.0f, bhz = 0.0f, bhn = 0.0f;
    if (tid < HID) {
        bhr = b_hh[tid];
        bhz = b_hh[HID + tid];
        bhn = b_hh[2 * HID + tid];
    }

    for (int i = tid; i < T * 3 * HID; i += 600) sgi[i] = g_gi[i];
    if (tid < HID) h[tid] = g_h0[tid];
    __syncthreads();

    for (int t = 0; t < T; t++) {
        {
            const u64* h2 = (const u64*)(h + half * 50);
            u64 a0 = 0ull, a1 = 0ull;
#pragma unroll
            for (int k = 0; k < 12; k++) {
                ffma2(a0, w2[2 * k], h2[2 * k]);
                ffma2(a1, w2[2 * k + 1], h2[2 * k + 1]);
            }
            ffma2(a0, w2[24], h2[24]);
            ps[tid] = (f2_lo(a0) + f2_hi(a0)) + (f2_lo(a1) + f2_hi(a1));
        }
        __syncthreads();

        if (tid < HID) {
            float ghr = ps[tid]       + ps[tid + 300] + bhr;
            float ghz = ps[tid + 100] + ps[tid + 400] + bhz;
            float ghn = ps[tid + 200] + ps[tid + 500] + bhn;
            const float* gi = sgi + t * 300;
            float r = sigmoidf_(gi[tid] + ghr);
            float z = sigmoidf_(gi[HID + tid] + ghz);
            float a = gi[2 * HID + tid] + r * ghn;
            float ex = __expf(2.0f * a);
            float n = 1.0f - __fdividef(2.0f, ex + 1.0f);
            float hn = (1.0f - z) * n + z * h[tid];
            h[tid] = hn;
            g_H[t * HID + tid] = hn;
            // padded layout for k_logits: [t][half*52 + j]
            int idx = t * 104 + ((tid < 50) ? tid : (tid + 2));
            g_Hp[idx] = hn;
        }
        __syncthreads();
    }
}

// ---------------- K4: logits + per-step sum(exp) ----------------
// 256 threads, 3 blocks/SM target. Lane pair (l, l+16) shares one vocab row;
// half = lane>>4 covers k-chunk [half*50, half*50+50) padded to 52.
#define LB 256
__global__ void __launch_bounds__(LB, 3) k_logits(const float* __restrict__ w_out,
                                                  const float* __restrict__ b_out) {
    __shared__ __align__(16) float sH[T * 104];   // 24960 B
    __shared__ float ss[8 * T];                   // per-warp partial sums
    int tid = threadIdx.x;
    int wid = tid >> 5;
    int lane = tid & 31;
    int half = lane >> 4;
    int v = blockIdx.x * 128 + wid * 16 + (lane & 15);
    bool valid = (v < VOCAB);

    // weight loads first (25 LDG.64 each), overlap with sH staging
    u64 w2[26];
    float bo = 0.0f;
    if (valid) {
        const u64* wr = (const u64*)(w_out + (size_t)v * HID + half * 50);
#pragma unroll
        for (int k = 0; k < 25; k++) w2[k] = wr[k];
        if (half == 0) bo = b_out[v];
    }
    w2[25] = 0ull;  // pad (matches zero pads in sH)

    for (int i = tid; i < T * 104; i += LB) sH[i] = g_Hp[i];
    __syncthreads();

    for (int t = 0; t < T; t++) {
        const double2* h2 = (const double2*)(sH + t * 104 + half * 52);
        u64 a0 = f2_pack(bo, 0.0f), a1 = 0ull;
#pragma unroll
        for (int k = 0; k < 13; k++) {
            double2 d = h2[k];
            ffma2(a0, w2[2 * k],     (u64)__double_as_longlong(d.x));
            ffma2(a1, w2[2 * k + 1], (u64)__double_as_longlong(d.y));
        }
        float part = (f2_lo(a0) + f2_hi(a0)) + (f2_lo(a1) + f2_hi(a1));
        float logit = part + __shfl_xor_sync(0xffffffffu, part, 16);
        float e = (valid && half == 0) ? __expf(logit) : 0.0f;
#pragma unroll
        for (int off = 16; off; off >>= 1)
            e += __shfl_down_sync(0xffffffffu, e, off);
        if (lane == 0) ss[wid * T + t] = e;   // exclusive slot, no atomic
    }
    __syncthreads();
    if (tid < T) {
        float s = 0.0f;
#pragma unroll
        for (int w = 0; w < 8; w++) s += ss[w * T + tid];
        atomicAdd(&g_sumexp[tid], s);
    }
}

// ---------------- K5: token logits + final loss ----------------
__global__ void __launch_bounds__(512) k_final(const float* __restrict__ w_out,
                                               const float* __restrict__ b_out,
                                               const int* __restrict__ desc,
                                               float* __restrict__ out) {
    __shared__ float tl[T];
    __shared__ float red[16];
    int tid = threadIdx.x;
    int wid = tid >> 5;
    int lane = tid & 31;

    // warps 0..14 handle 4 timesteps each
#pragma unroll
    for (int i = 0; i < 4; i++) {
        int t = wid * 4 + i;
        if (t < T) {
            int tok = desc[t];
            const float* wr = w_out + (size_t)tok * HID;
            const float* hr = g_H + t * HID;
            float acc = wr[lane] * hr[lane]
                      + wr[lane + 32] * hr[lane + 32]
                      + wr[lane + 64] * hr[lane + 64];
            if (lane < 4) acc += wr[lane + 96] * hr[lane + 96];
#pragma unroll
            for (int off = 16; off; off >>= 1)
                acc += __shfl_down_sync(0xffffffffu, acc, off);
            if (lane == 0) tl[t] = acc + b_out[tok];
        }
    }
    __syncthreads();

    float v = 0.0f;
    if (tid < T) v = logf(g_sumexp[tid]) - tl[tid];
#pragma unroll
    for (int off = 16; off; off >>= 1)
        v += __shfl_down_sync(0xffffffffu, v, off);
    if (lane == 0) red[wid] = v;
    __syncthreads();
    if (tid == 0) out[0] = red[0] + red[1];
}

// ---------------- launch ----------------
extern "C" void kernel_launch(void* const* d_in, const int* in_sizes, int n_in,
                              void* d_out, int out_size) {
    const int*   context  = (const int*)d_in[0];
    const int*   desc     = (const int*)d_in[2];
    const float* emb_ctx  = (const float*)d_in[3];
    const float* emb_dec  = (const float*)d_in[4];
    const float* w1       = (const float*)d_in[5];
    const float* b1       = (const float*)d_in[6];
    const float* w_ih     = (const float*)d_in[7];
    const float* w_hh     = (const float*)d_in[8];
    const float* b_ih     = (const float*)d_in[9];
    const float* b_hh     = (const float*)d_in[10];
    const float* w_out    = (const float*)d_in[11];
    const float* b_out    = (const float*)d_in[12];
    float* out = (float*)d_out;

    const int rnn_smem = (T * 3 * HID + HID + 600) * (int)sizeof(float); // 74800 B
    cudaFuncSetAttribute(k_rnn, cudaFuncAttributeMaxDynamicSharedMemorySize, rnn_smem);

    k_pre<<<120, 320>>>(context, emb_ctx, desc, emb_dec, w_ih, b_ih);
    k_h0<<<HID, 256>>>(w1, b1);
    k_rnn<<<1, 600, rnn_smem>>>(w_hh, b_hh);
    k_logits<<<(VOCAB + 127) / 128, LB>>>(w_out, b_out);
    k_final<<<1, 512>>>(w_out, b_out, desc, out);
}